// round 8
// baseline (speedup 1.0000x reference)
#include <cuda_runtime.h>
#include <math.h>

// Fixed problem shape: B=8, N=48, D=2
#define BB 8
#define NN 48
#define MM (NN * NN)          // 2304 candidate pair-vectors per batch
#define T 1024                // threads per block (1 block per batch)
#define H 256                 // angle bins over [0, pi)
#define HALF (H / 2)
#define BINS_PER_LANE (H / 32)
#define PI_F 3.14159265358979f
#define INV_SCALE 9.313225746154785e-10f   // 2^-30  (histogram fixed point)
#define SCALE_F 1073741824.0f              // 2^30
#define S_SCALE 1048576.0                  // 2^20   (cross-block S fixed point)

// Scratch (allocations forbidden -> device globals)
__device__ unsigned long long g_sfx = 0ULL;   // sum of S * 2^20 (int, deterministic)
__device__ unsigned long long g_k2  = 0ULL;   // sum of K^2
__device__ int                g_ticket = 0;

__global__ __launch_bounds__(T, 1)
void fused_kernel(const float* __restrict__ gt,
                  const float* __restrict__ cs,
                  const float* __restrict__ thr,
                  float* __restrict__ out) {
    const int b    = blockIdx.x;
    const int tid  = threadIdx.x;
    const int lane = tid & 31;
    const int wid  = tid >> 5;

    __shared__ unsigned long long hx[H], hy[H];   // fixed-point bin resultants
    __shared__ float2 sg[NN];
    __shared__ float2 P[H];                       // inclusive prefix of bin vectors
    __shared__ float2 sVtot;
    __shared__ float  warp_acc[32];
    __shared__ int    warp_cnt[32];

    // Zero histogram (256 bins, threads 0..255 clear both arrays)
    if (tid < H) { hx[tid] = 0ULL; hy[tid] = 0ULL; }
    if (tid < NN) sg[tid] = ((const float2*)gt)[b * NN + tid];

    // Prefetch similarity values (2 full chunks + quarter chunk) + threshold
    float s0 = cs[b * MM + tid];
    float s1 = cs[b * MM + T + tid];
    float s2 = (tid < MM - 2 * T) ? cs[b * MM + 2 * T + tid] : -1e30f;
    const float t = thr[0];
    __syncthreads();

    // ---- element phase: normalize, angle-bin, histogram (deterministic int atomics)
    int cnt = 0;
    float sv[3] = {s0, s1, s2};
#pragma unroll
    for (int k = 0; k < 3; k++) {
        int idx = k * T + tid;
        float ss = sv[k];
        bool valid = (k < 2) || (tid < MM - 2 * T);
        if (valid && ss >= t) {                 // ref: where(cos < thr, 0, cos)
            int i = idx / NN;
            int j = idx - i * NN;
            float vx = (sg[i].x - sg[j].x) * ss;
            float vy = (sg[i].y - sg[j].y) * ss;
            if (vx != 0.f || vy != 0.f) {
                // per-element eps as in reference: sqrt(vx^2+eps + vy^2+eps)
                float inv = rsqrtf(vx * vx + 1e-9f + vy * vy + 1e-9f);
                float ux = vx * inv, uy = vy * inv;
                // fold to upper half-plane: theta in [0, pi)
                if (uy < 0.f || (uy == 0.f && ux < 0.f)) { ux = -ux; uy = -uy; }
                // octant-reduced atan (max err ~1e-6 rad)
                float ax = fabsf(ux);
                float mx = fmaxf(ax, uy);
                float mn = fminf(ax, uy);
                float tt = __fdividef(mn, mx);
                float t2 = tt * tt;
                float p = tt * (0.99997726f + t2 * (-0.33262347f + t2 * (0.19354346f
                         + t2 * (-0.11643287f + t2 * (0.05265332f + t2 * (-0.01172120f))))));
                float th = (uy > ax) ? (1.57079632679f - p) : p;
                th = (ux < 0.f) ? (PI_F - th) : th;
                int bin = (int)(th * ((float)H / PI_F));
                bin = max(0, min(H - 1, bin));
                atomicAdd(&hx[bin], (unsigned long long)(long long)(ux * SCALE_F));
                atomicAdd(&hy[bin], (unsigned long long)(long long)(uy * SCALE_F));
                cnt++;
            }
        }
    }
    __syncthreads();

    // ---- single-warp inclusive prefix sum over the 256 bins ----
    if (wid == 0) {
        float2 c[BINS_PER_LANE];
        int base_bin = lane * BINS_PER_LANE;
#pragma unroll
        for (int i = 0; i < BINS_PER_LANE; i++) {
            c[i].x = (float)(long long)hx[base_bin + i] * INV_SCALE;
            c[i].y = (float)(long long)hy[base_bin + i] * INV_SCALE;
            if (i > 0) { c[i].x += c[i - 1].x; c[i].y += c[i - 1].y; }
        }
        float2 totv = c[BINS_PER_LANE - 1];
        float2 scv = totv;
#pragma unroll
        for (int d = 1; d < 32; d <<= 1) {
            float px = __shfl_up_sync(0xffffffffu, scv.x, d);
            float py = __shfl_up_sync(0xffffffffu, scv.y, d);
            if (lane >= d) { scv.x += px; scv.y += py; }
        }
        float bx = scv.x - totv.x, by = scv.y - totv.y;   // exclusive base
#pragma unroll
        for (int i = 0; i < BINS_PER_LANE; i++)
            P[base_bin + i] = make_float2(bx + c[i].x, by + c[i].y);
        if (lane == 31) sVtot = scv;
    }
    __syncthreads();

    // ---- per-bin evaluation: acc = V_p . (2*arcsum(p) - Vtot) ----
    float acc = 0.f;
    if (tid < H) {
        float2 Vtot = sVtot;
        float2 v;
        v.x = (float)(long long)hx[tid] * INV_SCALE;
        v.y = (float)(long long)hy[tid] * INV_SCALE;
        float2 phi = (tid >= HALF) ? Vtot : P[tid + HALF - 1];
        float2 plo = (tid >= HALF) ? P[tid - HALF] : make_float2(0.f, 0.f);
        float Ax = 2.f * (phi.x - plo.x) - Vtot.x;
        float Ay = 2.f * (phi.y - plo.y) - Vtot.y;
        acc = v.x * Ax + v.y * Ay;
    }

    // ---- block reduction (fixed order -> deterministic) ----
#pragma unroll
    for (int d = 16; d > 0; d >>= 1) {
        acc += __shfl_xor_sync(0xffffffffu, acc, d);
        cnt += __shfl_xor_sync(0xffffffffu, cnt, d);
    }
    if (lane == 0) { warp_acc[wid] = acc; warp_cnt[wid] = cnt; }
    __syncthreads();
    if (tid == 0) {
        float S = 0.f;
        long long K = 0;
#pragma unroll
        for (int w = 0; w < 32; w++) { S += warp_acc[w]; K += warp_cnt[w]; }
        // deterministic cross-block accumulation in fixed point
        atomicAdd(&g_sfx, (unsigned long long)(long long)((double)S * S_SCALE));
        atomicAdd(&g_k2,  (unsigned long long)(K * K));
        __threadfence();
        int ticket = atomicAdd(&g_ticket, 1);
        if (ticket == BB - 1) {
            __threadfence();
            double total   = (double)(long long)g_sfx * (1.0 / S_SCALE);
            double idx_num = (double)(long long)g_k2;
            out[0] = (float)(total / idx_num);
            // reset for next graph replay
            g_sfx = 0ULL;
            g_k2  = 0ULL;
            g_ticket = 0;
        }
    }
}

extern "C" void kernel_launch(void* const* d_in, const int* in_sizes, int n_in,
                              void* d_out, int out_size) {
    const float* gt  = (const float*)d_in[0];   // [8,48,2]
    const float* cs  = (const float*)d_in[1];   // [8,48,48]
    const float* thr = (const float*)d_in[2];   // [1]
    float* out = (float*)d_out;

    fused_kernel<<<BB, T>>>(gt, cs, thr, out);
}

// round 10
// speedup vs baseline: 1.1873x; 1.1873x over previous
#include <cuda_runtime.h>
#include <math.h>

// Fixed problem shape: B=8, N=48, D=2
#define BB 8
#define NN 48
#define MM (NN * NN)          // 2304 candidate pair-vectors per batch
#define T 1024                // threads per block (1 block per batch)
#define H 256                 // angle bins over [0, pi)
#define HALF (H / 2)
#define BPL (H / 32)          // bins per lane for warp 0
#define PI_F 3.14159265358979f

// Histogram packing (per shared-memory bin, 64-bit word):
//   [52:64) count   (max 2304 < 4096)
//   [26:52) sum of round(ux*4096) + 8192  (max 2304*12289 < 2^26 -> no carry)
//   [ 0:26) sum of round(uy*4096) + 8192
#define BIAS 8192
#define QSCALE 4096.0f
#define INV_Q  2.44140625e-4f   // 1/4096

// Global packing (single word, integer -> deterministic):
//   [60:64) block count, [26:60) S*2^8 (34 bits), [0:26) sum K^2 (26 bits)
__device__ unsigned long long g_pack = 0ULL;

__global__ __launch_bounds__(T, 1)
void fused_kernel(const float* __restrict__ gt,
                  const float* __restrict__ cs,
                  const float* __restrict__ thr,
                  float* __restrict__ out) {
    const int b    = blockIdx.x;
    const int tid  = threadIdx.x;
    const int lane = tid & 31;
    const int wid  = tid >> 5;

    __shared__ unsigned long long h[H];
    __shared__ float2 sg[NN];
    __shared__ float2 P[H];        // inclusive prefix of bin resultants

    if (tid < H) h[tid] = 0ULL;
    if (tid < NN) sg[tid] = ((const float2*)gt)[b * NN + tid];

    // Prefetch similarity values (2 full chunks + quarter chunk) + threshold
    float s0 = cs[b * MM + tid];
    float s1 = cs[b * MM + T + tid];
    float s2 = (tid < MM - 2 * T) ? cs[b * MM + 2 * T + tid] : -1e30f;
    const float t = thr[0];
    __syncthreads();

    // ---- element phase: normalize, angle-bin, ONE packed smem atomic/elem ----
    float sv[3] = {s0, s1, s2};
#pragma unroll
    for (int k = 0; k < 3; k++) {
        int idx = k * T + tid;
        float ss = sv[k];
        bool valid = (k < 2) || (tid < MM - 2 * T);
        if (valid && ss >= t) {                 // ref: where(cos < thr, 0, cos)
            int i = idx / NN;
            int j = idx - i * NN;
            float vx = (sg[i].x - sg[j].x) * ss;
            float vy = (sg[i].y - sg[j].y) * ss;
            if (vx != 0.f || vy != 0.f) {
                // per-element eps as in reference: sqrt(vx^2+eps + vy^2+eps)
                float inv = rsqrtf(vx * vx + 1e-9f + vy * vy + 1e-9f);
                float ux = vx * inv, uy = vy * inv;
                // fold to upper half-plane: theta in [0, pi)
                if (uy < 0.f || (uy == 0.f && ux < 0.f)) { ux = -ux; uy = -uy; }
                // octant-reduced atan (max err ~1e-6 rad)
                float ax = fabsf(ux);
                float mx = fmaxf(ax, uy);
                float mn = fminf(ax, uy);
                float tt = __fdividef(mn, mx);
                float t2 = tt * tt;
                float p = tt * (0.99997726f + t2 * (-0.33262347f + t2 * (0.19354346f
                         + t2 * (-0.11643287f + t2 * (0.05265332f + t2 * (-0.01172120f))))));
                float th = (uy > ax) ? (1.57079632679f - p) : p;
                th = (ux < 0.f) ? (PI_F - th) : th;
                int bin = (int)(th * ((float)H / PI_F));
                bin = max(0, min(H - 1, bin));
                unsigned ix = (unsigned)(int)(ux * QSCALE + ((float)BIAS + 0.5f));
                unsigned iy = (unsigned)(int)(uy * QSCALE + ((float)BIAS + 0.5f));
                unsigned long long val = (1ULL << 52)
                                       | ((unsigned long long)ix << 26)
                                       | (unsigned long long)iy;
                atomicAdd(&h[bin], val);
            }
        }
    }
    __syncthreads();

    // ---- warp 0 only: unpack, prefix-scan bins, evaluate, global finale ----
    if (wid == 0) {
        float vx[BPL], vy[BPL];
        float cx[BPL], cy[BPL];
        int base = lane * BPL;
        float px = 0.f, py = 0.f;
        int   pk = 0;
#pragma unroll
        for (int i = 0; i < BPL; i++) {
            unsigned long long raw = h[base + i];
            int cp = (int)(raw >> 52);
            int xf = (int)((raw >> 26) & 0x3FFFFFFULL);
            int yf = (int)(raw & 0x3FFFFFFULL);
            vx[i] = (float)(xf - cp * BIAS) * INV_Q;
            vy[i] = (float)(yf - cp * BIAS) * INV_Q;
            px += vx[i]; py += vy[i]; pk += cp;
            cx[i] = px;  cy[i] = py;
        }
        // warp inclusive scan of per-lane totals
        float scx = px, scy = py; int sck = pk;
#pragma unroll
        for (int d = 1; d < 32; d <<= 1) {
            float ax_ = __shfl_up_sync(0xffffffffu, scx, d);
            float ay_ = __shfl_up_sync(0xffffffffu, scy, d);
            int   ak_ = __shfl_up_sync(0xffffffffu, sck, d);
            if (lane >= d) { scx += ax_; scy += ay_; sck += ak_; }
        }
        float bx = scx - px, by = scy - py;   // exclusive base for this lane
#pragma unroll
        for (int i = 0; i < BPL; i++)
            P[base + i] = make_float2(bx + cx[i], by + cy[i]);
        float vtx = __shfl_sync(0xffffffffu, scx, 31);
        float vty = __shfl_sync(0xffffffffu, scy, 31);
        long long K = (long long)__shfl_sync(0xffffffffu, sck, 31);
        __syncwarp();

        // eval: acc = sum_p V_p . (2*arcsum(p) - Vtot)
        float acc = 0.f;
#pragma unroll
        for (int i = 0; i < BPL; i++) {
            int p = base + i;
            float2 phi = (p >= HALF) ? make_float2(vtx, vty) : P[p + HALF - 1];
            float2 plo = (p >= HALF) ? P[p - HALF] : make_float2(0.f, 0.f);
            float Ax = 2.f * (phi.x - plo.x) - vtx;
            float Ay = 2.f * (phi.y - plo.y) - vty;
            acc += vx[i] * Ax + vy[i] * Ay;
        }
#pragma unroll
        for (int d = 16; d > 0; d >>= 1)
            acc += __shfl_xor_sync(0xffffffffu, acc, d);

        if (lane == 0) {
            long long Sfix = (long long)(fmaxf(acc, 0.f) * 256.f + 0.5f);
            unsigned long long val = (1ULL << 60)
                                   | ((unsigned long long)Sfix << 26)
                                   | (unsigned long long)(K * K);
            unsigned long long old = atomicAdd(&g_pack, val);
            unsigned long long tot = old + val;
            if ((tot >> 60) == (unsigned long long)BB) {
                double S  = (double)((tot >> 26) & 0x3FFFFFFFFULL) * (1.0 / 256.0);
                double k2 = (double)(tot & 0x3FFFFFFULL);
                out[0] = (float)(S / k2);
                atomicExch(&g_pack, 0ULL);   // reset for next graph replay
            }
        }
    }
}

extern "C" void kernel_launch(void* const* d_in, const int* in_sizes, int n_in,
                              void* d_out, int out_size) {
    const float* gt  = (const float*)d_in[0];   // [8,48,2]
    const float* cs  = (const float*)d_in[1];   // [8,48,48]
    const float* thr = (const float*)d_in[2];   // [1]
    float* out = (float*)d_out;

    fused_kernel<<<BB, T>>>(gt, cs, thr, out);
}